// round 8
// baseline (speedup 1.0000x reference)
#include <cuda_runtime.h>
#include <cstdint>

// Problem constants
#define NF 8
#define NK 16
#define NY 16
#define NX 16
#define NP 32
#define NT 8
#define NB 64
#define VOL 65536          // elements per (b,f)

// Device globals (no allocation allowed)
__device__ float g_klat[NF*NK*NY];
__device__ float g_klon[NF*NK*NX];
__device__ float g_klev[NF*NK*NP];
__device__ float g_r[NF*NK];
__device__ float g_ipart[NF*NK*8];
__device__ float g_cpart[2048*1024];   // 8 MB: per-CTA C partials [bid][b*16+k]

__device__ __forceinline__ uint32_t f2tf32(float x) {
    uint32_t r; asm("cvt.rna.tf32.f32 %0, %1;" : "=r"(r) : "f"(x)); return r;
}
__device__ __forceinline__ void mma_tf32(float c[4], uint32_t a0, uint32_t a1,
                                         uint32_t a2, uint32_t a3,
                                         uint32_t b0, uint32_t b1) {
    asm volatile(
        "mma.sync.aligned.m16n8k8.row.col.f32.tf32.tf32.f32 "
        "{%0,%1,%2,%3},{%4,%5,%6,%7},{%8,%9},{%0,%1,%2,%3};"
        : "+f"(c[0]), "+f"(c[1]), "+f"(c[2]), "+f"(c[3])
        : "r"(a0), "r"(a1), "r"(a2), "r"(a3), "r"(b0), "r"(b1));
}

// ---------------------------------------------------------------------------
// Prep: 8 sub-CTAs per (f,k) (1024 CTAs). 1D tables + geometric ratio r +
// non-atomic integration partials; zeroes the output buffer.
// ---------------------------------------------------------------------------
__global__ __launch_bounds__(256)
void prep_kernel(const float* __restrict__ qw,
                 const float* __restrict__ mu_lat, const float* __restrict__ ls_lat,
                 const float* __restrict__ mu_lon, const float* __restrict__ ls_lon,
                 const float* __restrict__ mu_lev, const float* __restrict__ ls_lev,
                 const float* __restrict__ lt_time,
                 float* __restrict__ out)
{
    const int bid = blockIdx.x;
    const int fk  = bid >> 3;
    const int sub = bid & 7;
    const int tid = threadIdx.x;
    __shared__ float s_lat[NY], s_lon[NX], s_lev[NP];
    __shared__ float s_part[8];

    if (tid < 8) out[bid*8 + tid] = 0.f;   // zero out (1024*8 = 8192)

    if (tid < NY) {
        float c = -1.f + 2.f * (float)tid / (float)(NY - 1);
        float z = (c - mu_lat[fk]) / expf(ls_lat[fk]);
        float v = expf(-0.5f * z * z);
        s_lat[tid] = v;
        if (sub == 0) g_klat[fk*NY + tid] = v;
    } else if (tid < 32) {
        int x = tid - 16;
        float c = -1.f + 2.f * (float)x / (float)(NX - 1);
        float z = (c - mu_lon[fk]) / expf(ls_lon[fk]);
        float v = expf(-0.5f * z * z);
        s_lon[x] = v;
        if (sub == 0) g_klon[fk*NX + x] = v;
    } else if (tid < 64) {
        int p = tid - 32;
        float c = -1.f + 2.f * (float)p / (float)(NP - 1);
        float z = (c - mu_lev[fk]) / expf(ls_lev[fk]);
        float v = expf(-0.5f * z * z);
        s_lev[p] = v;
        if (sub == 0) g_klev[fk*NP + p] = v;
    }
    float tau = expf(lt_time[fk]) + 1e-6f;
    float r = expf(-1.f / tau);
    if (sub == 0 && tid == 0) g_r[fk] = r;
    __syncthreads();

    const float4* q4 = (const float4*)qw;
    float local = 0.f;
    #pragma unroll
    for (int it = 0; it < 4; ++it) {
        int idx = sub*1024 + it*256 + tid;
        float4 q0 = q4[idx*2];
        float4 q1 = q4[idx*2 + 1];
        float s = q1.w;
        s = fmaf(s, r, q1.z); s = fmaf(s, r, q1.y); s = fmaf(s, r, q1.x);
        s = fmaf(s, r, q0.w); s = fmaf(s, r, q0.z); s = fmaf(s, r, q0.y);
        s = fmaf(s, r, q0.x);
        int p = idx & 31, x = (idx >> 5) & 15, y = idx >> 9;
        local += s * (s_lat[y] * s_lon[x] * s_lev[p]);
    }
    #pragma unroll
    for (int o = 16; o; o >>= 1) local += __shfl_xor_sync(0xffffffffu, local, o);
    if ((tid & 31) == 0) s_part[tid >> 5] = local;
    __syncthreads();
    if (tid == 0) {
        float s = 0.f;
        #pragma unroll
        for (int w = 0; w < 8; ++w) s += s_part[w];
        g_ipart[bid] = s;
    }
}

// ---------------------------------------------------------------------------
// Main GEMM kernel: grid = 2048 (f = bid&7, sl = bid>>3 = one yx block).
// C[64 batches, 16 kernels] = patch[64, 256 pts] x W[256 pts, 16] via
// mma.sync m16n8k8 tf32. W built in smem from tables (free vs DRAM);
// A staged coalesced -> smem tf32 with conflict-free padded layout.
// Warps: (mt = wid&3) x (kh = wid>>2) split M-tiles x K-halves; acc = 8 regs.
// Partials written non-atomically to g_cpart; reduce_kernel combines.
// ---------------------------------------------------------------------------
__global__ __launch_bounds__(256)
void feat_kernel(const float* __restrict__ patch, const float* __restrict__ qw)
{
    __shared__ uint32_t Bs[256][20];      // [i_local][k] tf32 weights (padded)
    __shared__ uint32_t As[64][68];       // [b][i_sub] tf32 patch (padded)
    __shared__ float s_cl[16];
    __shared__ float s_part[4][16][16];

    const int bid  = blockIdx.x;
    const int f    = bid & 7;
    const int sl   = bid >> 3;            // yx index 0..255
    const int tid  = threadIdx.x;
    const int lane = tid & 31, wid = tid >> 5;
    const int g = lane >> 2, tg = lane & 3;
    const int mt = wid & 3, kh = wid >> 2;

    if (tid < 16) {
        const int fk = f*16 + tid;
        float integ = 0.f;
        #pragma unroll
        for (int i = 0; i < 8; ++i) integ += g_ipart[fk*8 + i];
        s_cl[tid] = g_klat[fk*NY + (sl >> 4)] * g_klon[fk*NX + (sl & 15)]
                    / (integ + 1e-4f);
    }
    __syncthreads();

    // Build B: W[i][k] = qw_i * klat*klon*klev*r^t / (integ+1e-4), tf32
    {
        const int p = (tid >> 3) & 31, t = tid & 7;
        const float qwv = qw[sl*256 + tid];
        #pragma unroll
        for (int kq = 0; kq < 4; ++kq) {
            uint4 pk;
            uint32_t* pe = (uint32_t*)&pk;
            #pragma unroll
            for (int e = 0; e < 4; ++e) {
                const int k = kq*4 + e;
                const float r = g_r[f*16 + k];
                const float r2 = r*r, r4 = r2*r2;
                float rt = 1.f;
                if (t & 1) rt *= r;
                if (t & 2) rt *= r2;
                if (t & 4) rt *= r4;
                const float kl = g_klev[(f*16 + k)*NP + p];
                pe[e] = f2tf32(qwv * kl * rt * s_cl[k]);
            }
            *(uint4*)&Bs[tid][kq*4] = pk;
        }
    }

    float acc[2][4] = {};
    const size_t bstride = (size_t)NF * VOL;   // batch row stride (floats)
    const float* abase = patch + (size_t)f * VOL + (size_t)sl * 256;

    for (int sub = 0; sub < 4; ++sub) {
        __syncthreads();      // Bs ready (sub 0) / prev As fully consumed
        // Stage A sub-tile: 64 rows x 64 cols, coalesced float4 -> tf32 smem
        #pragma unroll
        for (int it = 0; it < 4; ++it) {
            const int fidx = it*256 + tid;     // 1024 float4 tiles
            const int row = fidx >> 4;         // 16 float4 per row
            const int c4  = fidx & 15;
            const float4 v = *(const float4*)(abase + (size_t)row * bstride
                                              + sub*64 + c4*4);
            uint4 w;
            w.x = f2tf32(v.x); w.y = f2tf32(v.y);
            w.z = f2tf32(v.z); w.w = f2tf32(v.w);
            *(uint4*)&As[row][c4*4] = w;
        }
        __syncthreads();

        // MMA: warp (mt,kh); k-tiles j -> local col (kh*4+j)*8
        #pragma unroll
        for (int j = 0; j < 4; ++j) {
            const int icl = (kh*4 + j)*8;      // col in As (0..63)
            const int icb = sub*64 + icl;      // row in Bs (0..255)
            uint32_t a0 = As[mt*16 + g    ][icl + tg];
            uint32_t a1 = As[mt*16 + g + 8][icl + tg];
            uint32_t a2 = As[mt*16 + g    ][icl + tg + 4];
            uint32_t a3 = As[mt*16 + g + 8][icl + tg + 4];
            uint32_t b0 = Bs[icb + tg    ][g];
            uint32_t b1 = Bs[icb + tg + 4][g];
            uint32_t c0 = Bs[icb + tg    ][g + 8];
            uint32_t c1 = Bs[icb + tg + 4][g + 8];
            mma_tf32(acc[0], a0, a1, a2, a3, b0, b1);
            mma_tf32(acc[1], a0, a1, a2, a3, c0, c1);
        }
    }

    // Pair-reduce the two K-halves, then store partials (no atomics)
    if (kh == 1) {
        s_part[mt][g    ][tg*2    ] = acc[0][0];
        s_part[mt][g    ][tg*2 + 1] = acc[0][1];
        s_part[mt][g + 8][tg*2    ] = acc[0][2];
        s_part[mt][g + 8][tg*2 + 1] = acc[0][3];
        s_part[mt][g    ][8 + tg*2    ] = acc[1][0];
        s_part[mt][g    ][8 + tg*2 + 1] = acc[1][1];
        s_part[mt][g + 8][8 + tg*2    ] = acc[1][2];
        s_part[mt][g + 8][8 + tg*2 + 1] = acc[1][3];
    }
    __syncthreads();
    if (kh == 0) {
        float* dst = g_cpart + (size_t)bid * 1024;
        const int r0 = mt*16 + g, r1 = r0 + 8;
        dst[r0*16 + tg*2    ] = acc[0][0] + s_part[mt][g    ][tg*2    ];
        dst[r0*16 + tg*2 + 1] = acc[0][1] + s_part[mt][g    ][tg*2 + 1];
        dst[r1*16 + tg*2    ] = acc[0][2] + s_part[mt][g + 8][tg*2    ];
        dst[r1*16 + tg*2 + 1] = acc[0][3] + s_part[mt][g + 8][tg*2 + 1];
        dst[r0*16 + 8 + tg*2    ] = acc[1][0] + s_part[mt][g    ][8 + tg*2    ];
        dst[r0*16 + 8 + tg*2 + 1] = acc[1][1] + s_part[mt][g    ][8 + tg*2 + 1];
        dst[r1*16 + 8 + tg*2    ] = acc[1][2] + s_part[mt][g + 8][8 + tg*2    ];
        dst[r1*16 + 8 + tg*2 + 1] = acc[1][3] + s_part[mt][g + 8][8 + tg*2 + 1];
    }
}

// ---------------------------------------------------------------------------
// Reduce: out[b*128 + f*16 + k] += sum over 256 yx slices of g_cpart.
// Grid 256: (sl-group = bid>>5 of 32 slices) x (output block = bid&31).
// out was zeroed by prep; 8 atomicAdds per output address total.
// ---------------------------------------------------------------------------
__global__ __launch_bounds__(256)
void reduce_kernel(float* __restrict__ out)
{
    const int bid = blockIdx.x;
    const int sg  = bid >> 5;                 // 0..7
    const int o   = (bid & 31) * 256 + threadIdx.x;   // 0..8191
    const int b   = o >> 7;
    const int fk  = o & 127;                  // f*16 + k
    const int f   = fk >> 4;

    const float* src = g_cpart + (size_t)f*1024 + (size_t)b*16 + (fk & 15);
    float s0 = 0.f, s1 = 0.f, s2 = 0.f, s3 = 0.f;
    #pragma unroll
    for (int i = 0; i < 8; ++i) {
        const int sl = sg*32 + i*4;
        s0 += src[(size_t)(sl    ) * 8192];
        s1 += src[(size_t)(sl + 1) * 8192];
        s2 += src[(size_t)(sl + 2) * 8192];
        s3 += src[(size_t)(sl + 3) * 8192];
    }
    atomicAdd(&out[o], (s0 + s1) + (s2 + s3));
}

// ---------------------------------------------------------------------------
// Launch. Inputs (metadata order): patch, quadweights, mu_lat, logsigma_lat,
// mu_lon, logsigma_lon, mu_lev, logsigma_lev, logtau_time.
// ---------------------------------------------------------------------------
extern "C" void kernel_launch(void* const* d_in, const int* in_sizes, int n_in,
                              void* d_out, int out_size)
{
    (void)in_sizes; (void)n_in; (void)out_size;
    const float* patch  = (const float*)d_in[0];
    const float* qw     = (const float*)d_in[1];
    const float* mu_lat = (const float*)d_in[2];
    const float* ls_lat = (const float*)d_in[3];
    const float* mu_lon = (const float*)d_in[4];
    const float* ls_lon = (const float*)d_in[5];
    const float* mu_lev = (const float*)d_in[6];
    const float* ls_lev = (const float*)d_in[7];
    const float* lt     = (const float*)d_in[8];
    float* out = (float*)d_out;

    prep_kernel<<<NF*NK*8, 256>>>(qw, mu_lat, ls_lat, mu_lon, ls_lon,
                                  mu_lev, ls_lev, lt, out);
    feat_kernel<<<2048, 256>>>(patch, qw);
    reduce_kernel<<<256, 256>>>(out);
}